// round 9
// baseline (speedup 1.0000x reference)
#include <cuda_runtime.h>
#include <cuda_fp16.h>
#include <cstdint>

// StyleGAN2 modulated+demodulated conv on GB300 (sm_103 base target -> HMMA).
// x: (8,128,128,128) NHWC fp32, style: (8,128), kernel: (3,3,128,128) -> NHWC fp32
//
// Single-product fp16 GEMM: Y = fp16(X) * fp16(W_mod_demod), fp32 accum.
// K0 prep : fused [X fp32->fp16] + [demod scale + modulate -> fp16 W, [b][f][k]]
// K1 gemm : per (h,b) CTA: M=128 (w), N=128 (f), K=1152.
//   A from 130-row shifted windows (one per (dy, c-half) stage, 6 stages; all
//   3 dx taps served by smem row offset). B: 18 chunks of 64, 4-deep cp.async
//   pipeline (wait_group 2). Cross-chunk ldmatrix fragment prefetch.
//   4 warps, warp tile 64x64, 2 CTAs/SM.

#define HW    128
#define CIN   128
#define FOUT  128
#define BATCH 8
#define KK    1152
#define NCH   18

__device__ __half g_xh[BATCH * HW * HW * CIN];
__device__ __half g_wh[BATCH * FOUT * KK];

// ---------------- asm helpers ----------------
__device__ __forceinline__ uint32_t smem_u32(const void* p) {
    uint32_t a;
    asm("{ .reg .u64 t; cvta.to.shared.u64 t, %1; cvt.u32.u64 %0, t; }"
        : "=r"(a) : "l"(p));
    return a;
}
__device__ __forceinline__ void ldsm4(uint32_t* r, uint32_t addr) {
    asm volatile("ldmatrix.sync.aligned.m8n8.x4.shared.b16 {%0,%1,%2,%3}, [%4];"
                 : "=r"(r[0]), "=r"(r[1]), "=r"(r[2]), "=r"(r[3]) : "r"(addr));
}
__device__ __forceinline__ void mma_f16(float* c, const uint32_t* a, const uint32_t* b) {
    asm volatile(
        "mma.sync.aligned.m16n8k16.row.col.f32.f16.f16.f32 "
        "{%0,%1,%2,%3}, {%4,%5,%6,%7}, {%8,%9}, {%0,%1,%2,%3};"
        : "+f"(c[0]), "+f"(c[1]), "+f"(c[2]), "+f"(c[3])
        : "r"(a[0]), "r"(a[1]), "r"(a[2]), "r"(a[3]), "r"(b[0]), "r"(b[1]));
}
__device__ __forceinline__ void cp_async16z(uint32_t saddr, const void* gaddr,
                                            uint32_t src_size) {
    asm volatile("cp.async.cg.shared.global [%0], [%1], 16, %2;"
                 :: "r"(saddr), "l"(gaddr), "r"(src_size));
}
__device__ __forceinline__ void cp_async16(uint32_t saddr, const void* gaddr) {
    asm volatile("cp.async.cg.shared.global [%0], [%1], 16;"
                 :: "r"(saddr), "l"(gaddr));
}
__device__ __forceinline__ void cp_commit() { asm volatile("cp.async.commit_group;"); }
#define CP_WAIT(n) asm volatile("cp.async.wait_group %0;" :: "n"(n) : "memory")

// ---------------------------------------------------------------------------
// K0: fused prep. Blocks [0, 8192): X fp32 -> fp16 (8 floats/thread).
//     Blocks [8192, 8704): wprep, 2 f-columns per block (256 threads).
// ---------------------------------------------------------------------------
#define SPLIT_BLOCKS 8192
__global__ void prep_kernel(const float* __restrict__ X,
                            const float* __restrict__ style,
                            const float* __restrict__ kern) {
    if (blockIdx.x < SPLIT_BLOCKS) {
        size_t i = ((size_t)blockIdx.x * 256 + threadIdx.x) * 8;
        float4 v0 = *(const float4*)(X + i);
        float4 v1 = *(const float4*)(X + i + 4);
        __half2 h01 = __floats2half2_rn(v0.x, v0.y);
        __half2 h23 = __floats2half2_rn(v0.z, v0.w);
        __half2 h45 = __floats2half2_rn(v1.x, v1.y);
        __half2 h67 = __floats2half2_rn(v1.z, v1.w);
        uint4 o = make_uint4(*(uint32_t*)&h01, *(uint32_t*)&h23,
                             *(uint32_t*)&h45, *(uint32_t*)&h67);
        *(uint4*)(g_xh + i) = o;
        return;
    }
    // wprep: block handles (b, f0..f0+1)
    const int wb   = blockIdx.x - SPLIT_BLOCKS;      // 0..511
    const int b    = wb >> 6;                        // 0..7
    const int f    = (wb & 63) * 2 + (threadIdx.x >> 7);
    const int c    = threadIdx.x & 127;
    const int half = threadIdx.x >> 7;
    const float st = style[b * CIN + c] + 1.0f;
    float wv[9];
    float ss = 0.0f;
    #pragma unroll
    for (int p = 0; p < 9; ++p) {
        float w = kern[(p * 128 + c) * 128 + f] * st;
        wv[p] = w;
        ss = fmaf(w, w, ss);
    }
    __shared__ float red[2][128];
    red[half][c] = ss;
    __syncthreads();
    #pragma unroll
    for (int s = 64; s > 0; s >>= 1) {
        if (c < s) red[half][c] += red[half][c + s];
        __syncthreads();
    }
    const float scale = rsqrtf(red[half][0] + 1e-8f);
    const size_t base = (size_t)(b * 128 + f) * KK;
    #pragma unroll
    for (int p = 0; p < 9; ++p)
        g_wh[base + p * 128 + c] = __float2half_rn(wv[p] * scale);
}

// ---------------------------------------------------------------------------
// K1: HMMA implicit GEMM with shifted-window A.
// grid (128 h, 8 b) x 128 threads (4 warps), 2 CTAs/SM.
// Warps 2(m) x 2(n), warp tile 64x64.
// SMEM: A windows 2 x 17408 (130 rows x 128B, SW128), B 4 x 16384.
// ---------------------------------------------------------------------------
#define ABUF_BYTES 17408
#define BBUF_BYTES 16384
#define SMEM_B0    (2 * ABUF_BYTES)               // 34816
#define SMEM_TOTAL (SMEM_B0 + 4 * BBUF_BYTES)     // 100352

__global__ __launch_bounds__(128, 2)
void mdconv_hmma_kernel(float* __restrict__ Y) {
    extern __shared__ __align__(1024) char smem[];
    const uint32_t sb  = smem_u32(smem);
    const int tid  = threadIdx.x;
    const int wid  = tid >> 5;
    const int lane = tid & 31;
    const int h = blockIdx.x;
    const int b = blockIdx.y;

    const int mw = (wid >> 1) * 64;     // warp m offset
    const int nw = (wid & 1) * 64;      // warp n offset

    const __half* xh_b = g_xh + (size_t)b * HW * HW * CIN;
    const __half* wh_b = g_wh + (size_t)b * FOUT * KK;

    // ---- ldmatrix per-lane invariants ----
    const int arow_l = (lane & 7) + ((lane >> 3) & 1) * 8;
    const int akb_l  = ((lane >> 4) & 1) * 16;
    const int brow_l = (lane & 7) + ((lane >> 4) & 1) * 8;
    const int bkb_l  = ((lane >> 3) & 1) * 16;

    int aRowBase[4];
    #pragma unroll
    for (int mt = 0; mt < 4; ++mt) aRowBase[mt] = mw + mt * 16 + arow_l;
    uint32_t bRowOff[4], bXor[4];
    #pragma unroll
    for (int np = 0; np < 4; ++np) {
        const int row = nw + np * 16 + brow_l;
        bRowOff[np] = (uint32_t)row * 128;
        bXor[np]    = (uint32_t)((row & 7) * 16);
    }

    float acc[4][8][4];
    #pragma unroll
    for (int i = 0; i < 4; ++i)
        #pragma unroll
        for (int j = 0; j < 8; ++j)
            #pragma unroll
            for (int q = 0; q < 4; ++q) acc[i][j][q] = 0.0f;

    // A window for stage s_: 130 rows (w=-1..128) x 64 ch of X[h+dy][.][c0..]
    #define ISSUE_A(s_)                                                       \
    {                                                                         \
        const uint32_t abuf = sb + (uint32_t)((s_) & 1) * ABUF_BYTES;         \
        const int dy_ = (s_) / 2 - 1;                                         \
        const int c0_ = ((s_) & 1) * 64;                                      \
        const int hh_ = h + dy_;                                              \
        const bool hok_ = (unsigned)hh_ < HW;                                 \
        _Pragma("unroll")                                                     \
        for (int t = 0; t < 8; ++t) {                                         \
            const int u = tid + 128 * t;                                      \
            const int row = u >> 3, seg = u & 7;                              \
            const int wq = row - 1;                                           \
            const bool ok = hok_ && ((unsigned)wq < HW);                      \
            const __half* ga = ok                                             \
                ? xh_b + (((size_t)hh_ * HW + wq) << 7) + c0_ + seg * 8       \
                : xh_b;                                                       \
            cp_async16z(abuf + row * 128 + ((seg * 16) ^ ((row & 7) * 16)),   \
                        ga, ok ? 16u : 0u);                                   \
        }                                                                     \
        if (tid < 16) {                                                       \
            const int u = 1024 + tid;                                         \
            const int row = u >> 3, seg = u & 7;                              \
            const int wq = row - 1;                                           \
            const bool ok = hok_ && ((unsigned)wq < HW);                      \
            const __half* ga = ok                                             \
                ? xh_b + (((size_t)hh_ * HW + wq) << 7) + c0_ + seg * 8       \
                : xh_b;                                                       \
            cp_async16z(abuf + row * 128 + ((seg * 16) ^ ((row & 7) * 16)),   \
                        ga, ok ? 16u : 0u);                                   \
        }                                                                     \
    }

    #define ISSUE_B(kc_)                                                      \
    {                                                                         \
        const uint32_t bbuf = sb + SMEM_B0                                    \
                            + (uint32_t)((kc_) & 3) * BBUF_BYTES;             \
        const int s_  = (kc_) / 3;                                            \
        const int p_  = (s_ / 2) * 3 + (kc_) % 3;                             \
        const int c0_ = (s_ & 1) * 64;                                        \
        _Pragma("unroll")                                                     \
        for (int t = 0; t < 8; ++t) {                                         \
            const int u = tid + 128 * t;                                      \
            const int f_ = u >> 3, seg = u & 7;                               \
            cp_async16(bbuf + f_ * 128 + ((seg * 16) ^ ((f_ & 7) * 16)),      \
                       wh_b + (size_t)f_ * KK + p_ * 128 + c0_ + seg * 8);    \
        }                                                                     \
    }

    #define LOAD_A_FRAGS(bf_, abuf_, dxp1_, ks_)                              \
    {                                                                         \
        _Pragma("unroll")                                                     \
        for (int mt = 0; mt < 4; ++mt) {                                      \
            const int row = aRowBase[mt] + (dxp1_);                           \
            const uint32_t off = (uint32_t)row * 128                          \
                + ((uint32_t)((ks_) * 32 + akb_l) ^ ((row & 7) * 16));        \
            ldsm4(Af[bf_][mt], (abuf_) + off);                                \
        }                                                                     \
    }
    #define LOAD_B_FRAGS(bf_, bbuf_, ks_)                                     \
    {                                                                         \
        _Pragma("unroll")                                                     \
        for (int np = 0; np < 4; ++np)                                        \
            ldsm4(Bf[bf_][np], (bbuf_) + bRowOff[np]                          \
                  + ((uint32_t)((ks_) * 32 + bkb_l) ^ bXor[np]));             \
    }

    // ---- prologue: g0={A0,B0}, g1={B1}, g2={B2} ----
    ISSUE_A(0); ISSUE_B(0); cp_commit();
    ISSUE_B(1); cp_commit();
    ISSUE_B(2); cp_commit();

    uint32_t Af[2][4][4], Bf[2][4][4];

    for (int kc = 0; kc < NCH; ++kc) {
        CP_WAIT(2);
        __syncthreads();

        const int s    = kc / 3;
        const int dxp1 = kc % 3;
        const uint32_t abuf = sb + (uint32_t)(s & 1) * ABUF_BYTES;
        const uint32_t bbuf = sb + SMEM_B0 + (uint32_t)(kc & 3) * BBUF_BYTES;

        // prefetch ks=0 fragments, then issue next loads (overlaps LDSM latency)
        LOAD_A_FRAGS(0, abuf, dxp1, 0);
        LOAD_B_FRAGS(0, bbuf, 0);

        if (kc % 3 == 0 && (s + 1) < 6) ISSUE_A(s + 1);
        if (kc + 3 < NCH) ISSUE_B(kc + 3);
        cp_commit();

        #pragma unroll
        for (int ks = 0; ks < 4; ++ks) {
            const int cur = ks & 1;
            if (ks < 3) {
                LOAD_A_FRAGS(cur ^ 1, abuf, dxp1, ks + 1);
                LOAD_B_FRAGS(cur ^ 1, bbuf, ks + 1);
            }
            #pragma unroll
            for (int mt = 0; mt < 4; ++mt)
                #pragma unroll
                for (int np = 0; np < 4; ++np) {
                    mma_f16(acc[mt][np * 2],     Af[cur][mt], &Bf[cur][np][0]);
                    mma_f16(acc[mt][np * 2 + 1], Af[cur][mt], &Bf[cur][np][2]);
                }
        }
    }

    // ---- epilogue: direct STG ----
    float* Yb = Y + (((size_t)b * HW + h) * HW) * FOUT;
    #pragma unroll
    for (int mt = 0; mt < 4; ++mt)
        #pragma unroll
        for (int rg = 0; rg < 2; ++rg) {
            const int m = mw + mt * 16 + rg * 8 + (lane >> 2);
            float* yr = Yb + (size_t)m * FOUT + nw + (lane & 3) * 2;
            #pragma unroll
            for (int nt = 0; nt < 8; ++nt) {
                float2 v;
                v.x = acc[mt][nt][rg * 2];
                v.y = acc[mt][nt][rg * 2 + 1];
                *(float2*)(yr + nt * 8) = v;
            }
        }
    #undef ISSUE_A
    #undef ISSUE_B
    #undef LOAD_A_FRAGS
    #undef LOAD_B_FRAGS
}

// ---------------------------------------------------------------------------
extern "C" void kernel_launch(void* const* d_in, const int* in_sizes, int n_in,
                              void* d_out, int out_size) {
    const float* x     = (const float*)d_in[0];   // (8,128,128,128)
    const float* style = (const float*)d_in[1];   // (8,128)
    const float* kern  = (const float*)d_in[2];   // (3,3,128,128)
    float* y = (float*)d_out;

    cudaFuncSetAttribute(mdconv_hmma_kernel,
                         cudaFuncAttributeMaxDynamicSharedMemorySize, SMEM_TOTAL);

    prep_kernel<<<SPLIT_BLOCKS + 512, 256>>>(x, style, kern);
    mdconv_hmma_kernel<<<dim3(HW, BATCH), 128, SMEM_TOTAL>>>(y);
}

// round 10
// speedup vs baseline: 1.0294x; 1.0294x over previous
#include <cuda_runtime.h>
#include <cuda_fp16.h>
#include <cstdint>

// StyleGAN2 modulated+demodulated conv on GB300 (sm_103 base target -> HMMA).
// x: (8,128,128,128) NHWC fp32, style: (8,128), kernel: (3,3,128,128) -> NHWC fp32
//
// Single-product fp16 GEMM: Y = fp16(X) * fp16(W_mod_demod), fp32 accum.
// K0 split_x: X fp32 -> fp16  (separate kernel: fused version regressed, R8)
// K1 wprep  : demod scale + modulate -> fp16 W, layout [b][f][k]
// K2 gemm   : per (h,b) CTA: M=128 (w), N=128 (f), K=1152.
//   A from 130-row shifted windows (one per (dy, c-half) stage, 6 stages; all
//   3 dx taps served by smem row offset). B: 18 chunks of 64, 4-deep cp.async
//   pipeline (wait_group 2). Cross-chunk ldmatrix fragment prefetch.
//   4 warps, warp tile 64x64, 2 CTAs/SM.

#define HW    128
#define CIN   128
#define FOUT  128
#define BATCH 8
#define KK    1152
#define NCH   18

__device__ __half g_xh[BATCH * HW * HW * CIN];
__device__ __half g_wh[BATCH * FOUT * KK];

// ---------------- asm helpers ----------------
__device__ __forceinline__ uint32_t smem_u32(const void* p) {
    uint32_t a;
    asm("{ .reg .u64 t; cvta.to.shared.u64 t, %1; cvt.u32.u64 %0, t; }"
        : "=r"(a) : "l"(p));
    return a;
}
__device__ __forceinline__ void ldsm4(uint32_t* r, uint32_t addr) {
    asm volatile("ldmatrix.sync.aligned.m8n8.x4.shared.b16 {%0,%1,%2,%3}, [%4];"
                 : "=r"(r[0]), "=r"(r[1]), "=r"(r[2]), "=r"(r[3]) : "r"(addr));
}
__device__ __forceinline__ void mma_f16(float* c, const uint32_t* a, const uint32_t* b) {
    asm volatile(
        "mma.sync.aligned.m16n8k16.row.col.f32.f16.f16.f32 "
        "{%0,%1,%2,%3}, {%4,%5,%6,%7}, {%8,%9}, {%0,%1,%2,%3};"
        : "+f"(c[0]), "+f"(c[1]), "+f"(c[2]), "+f"(c[3])
        : "r"(a[0]), "r"(a[1]), "r"(a[2]), "r"(a[3]), "r"(b[0]), "r"(b[1]));
}
__device__ __forceinline__ void cp_async16z(uint32_t saddr, const void* gaddr,
                                            uint32_t src_size) {
    asm volatile("cp.async.cg.shared.global [%0], [%1], 16, %2;"
                 :: "r"(saddr), "l"(gaddr), "r"(src_size));
}
__device__ __forceinline__ void cp_async16(uint32_t saddr, const void* gaddr) {
    asm volatile("cp.async.cg.shared.global [%0], [%1], 16;"
                 :: "r"(saddr), "l"(gaddr));
}
__device__ __forceinline__ void cp_commit() { asm volatile("cp.async.commit_group;"); }
#define CP_WAIT(n) asm volatile("cp.async.wait_group %0;" :: "n"(n) : "memory")

// ---------------------------------------------------------------------------
// K0: X fp32 -> fp16 (8 floats/thread).
// ---------------------------------------------------------------------------
__global__ void split_x_kernel(const float* __restrict__ X) {
    size_t i = ((size_t)blockIdx.x * 256 + threadIdx.x) * 8;
    float4 v0 = *(const float4*)(X + i);
    float4 v1 = *(const float4*)(X + i + 4);
    __half2 h01 = __floats2half2_rn(v0.x, v0.y);
    __half2 h23 = __floats2half2_rn(v0.z, v0.w);
    __half2 h45 = __floats2half2_rn(v1.x, v1.y);
    __half2 h67 = __floats2half2_rn(v1.z, v1.w);
    uint4 o = make_uint4(*(uint32_t*)&h01, *(uint32_t*)&h23,
                         *(uint32_t*)&h45, *(uint32_t*)&h67);
    *(uint4*)(g_xh + i) = o;
}

// ---------------------------------------------------------------------------
// K1: fused demod scale + modulate -> fp16, layout [b][f][k].
// grid (128 f, 8 b) x 128 threads (c).
// ---------------------------------------------------------------------------
__global__ void wprep_kernel(const float* __restrict__ style,
                             const float* __restrict__ kern) {
    const int f = blockIdx.x, b = blockIdx.y, c = threadIdx.x;
    const float st = style[b * CIN + c] + 1.0f;
    float wv[9];
    float ss = 0.0f;
    #pragma unroll
    for (int p = 0; p < 9; ++p) {
        float w = kern[(p * 128 + c) * 128 + f] * st;
        wv[p] = w;
        ss = fmaf(w, w, ss);
    }
    __shared__ float red[128];
    red[c] = ss;
    __syncthreads();
    #pragma unroll
    for (int s = 64; s > 0; s >>= 1) {
        if (c < s) red[c] += red[c + s];
        __syncthreads();
    }
    const float scale = rsqrtf(red[0] + 1e-8f);
    const size_t base = (size_t)(b * 128 + f) * KK;
    #pragma unroll
    for (int p = 0; p < 9; ++p)
        g_wh[base + p * 128 + c] = __float2half_rn(wv[p] * scale);
}

// ---------------------------------------------------------------------------
// K2: HMMA implicit GEMM with shifted-window A.
// grid (128 h, 8 b) x 128 threads (4 warps), 2 CTAs/SM.
// Warps 2(m) x 2(n), warp tile 64x64.
// SMEM: A windows 2 x 17408 (130 rows x 128B, SW128), B 4 x 16384.
// ---------------------------------------------------------------------------
#define ABUF_BYTES 17408
#define BBUF_BYTES 16384
#define SMEM_B0    (2 * ABUF_BYTES)               // 34816
#define SMEM_TOTAL (SMEM_B0 + 4 * BBUF_BYTES)     // 100352

__global__ __launch_bounds__(128, 2)
void mdconv_hmma_kernel(float* __restrict__ Y) {
    extern __shared__ __align__(1024) char smem[];
    const uint32_t sb  = smem_u32(smem);
    const int tid  = threadIdx.x;
    const int wid  = tid >> 5;
    const int lane = tid & 31;
    const int h = blockIdx.x;
    const int b = blockIdx.y;

    const int mw = (wid >> 1) * 64;     // warp m offset
    const int nw = (wid & 1) * 64;      // warp n offset

    const __half* xh_b = g_xh + (size_t)b * HW * HW * CIN;
    const __half* wh_b = g_wh + (size_t)b * FOUT * KK;

    // ---- ldmatrix per-lane invariants ----
    const int arow_l = (lane & 7) + ((lane >> 3) & 1) * 8;
    const int akb_l  = ((lane >> 4) & 1) * 16;
    const int brow_l = (lane & 7) + ((lane >> 4) & 1) * 8;
    const int bkb_l  = ((lane >> 3) & 1) * 16;

    int aRowBase[4];
    #pragma unroll
    for (int mt = 0; mt < 4; ++mt) aRowBase[mt] = mw + mt * 16 + arow_l;
    uint32_t bRowOff[4], bXor[4];
    #pragma unroll
    for (int np = 0; np < 4; ++np) {
        const int row = nw + np * 16 + brow_l;
        bRowOff[np] = (uint32_t)row * 128;
        bXor[np]    = (uint32_t)((row & 7) * 16);
    }

    float acc[4][8][4];
    #pragma unroll
    for (int i = 0; i < 4; ++i)
        #pragma unroll
        for (int j = 0; j < 8; ++j)
            #pragma unroll
            for (int q = 0; q < 4; ++q) acc[i][j][q] = 0.0f;

    // A window for stage s_: 130 rows (w=-1..128) x 64 ch of X[h+dy][.][c0..]
    #define ISSUE_A(s_)                                                       \
    {                                                                         \
        const uint32_t abuf = sb + (uint32_t)((s_) & 1) * ABUF_BYTES;         \
        const int dy_ = (s_) / 2 - 1;                                         \
        const int c0_ = ((s_) & 1) * 64;                                      \
        const int hh_ = h + dy_;                                              \
        const bool hok_ = (unsigned)hh_ < HW;                                 \
        _Pragma("unroll")                                                     \
        for (int t = 0; t < 8; ++t) {                                         \
            const int u = tid + 128 * t;                                      \
            const int row = u >> 3, seg = u & 7;                              \
            const int wq = row - 1;                                           \
            const bool ok = hok_ && ((unsigned)wq < HW);                      \
            const __half* ga = ok                                             \
                ? xh_b + (((size_t)hh_ * HW + wq) << 7) + c0_ + seg * 8       \
                : xh_b;                                                       \
            cp_async16z(abuf + row * 128 + ((seg * 16) ^ ((row & 7) * 16)),   \
                        ga, ok ? 16u : 0u);                                   \
        }                                                                     \
        if (tid < 16) {                                                       \
            const int u = 1024 + tid;                                         \
            const int row = u >> 3, seg = u & 7;                              \
            const int wq = row - 1;                                           \
            const bool ok = hok_ && ((unsigned)wq < HW);                      \
            const __half* ga = ok                                             \
                ? xh_b + (((size_t)hh_ * HW + wq) << 7) + c0_ + seg * 8       \
                : xh_b;                                                       \
            cp_async16z(abuf + row * 128 + ((seg * 16) ^ ((row & 7) * 16)),   \
                        ga, ok ? 16u : 0u);                                   \
        }                                                                     \
    }

    #define ISSUE_B(kc_)                                                      \
    {                                                                         \
        const uint32_t bbuf = sb + SMEM_B0                                    \
                            + (uint32_t)((kc_) & 3) * BBUF_BYTES;             \
        const int s_  = (kc_) / 3;                                            \
        const int p_  = (s_ / 2) * 3 + (kc_) % 3;                             \
        const int c0_ = (s_ & 1) * 64;                                        \
        _Pragma("unroll")                                                     \
        for (int t = 0; t < 8; ++t) {                                         \
            const int u = tid + 128 * t;                                      \
            const int f_ = u >> 3, seg = u & 7;                               \
            cp_async16(bbuf + f_ * 128 + ((seg * 16) ^ ((f_ & 7) * 16)),      \
                       wh_b + (size_t)f_ * KK + p_ * 128 + c0_ + seg * 8);    \
        }                                                                     \
    }

    #define LOAD_A_FRAGS(bf_, abuf_, dxp1_, ks_)                              \
    {                                                                         \
        _Pragma("unroll")                                                     \
        for (int mt = 0; mt < 4; ++mt) {                                      \
            const int row = aRowBase[mt] + (dxp1_);                           \
            const uint32_t off = (uint32_t)row * 128                          \
                + ((uint32_t)((ks_) * 32 + akb_l) ^ ((row & 7) * 16));        \
            ldsm4(Af[bf_][mt], (abuf_) + off);                                \
        }                                                                     \
    }
    #define LOAD_B_FRAGS(bf_, bbuf_, ks_)                                     \
    {                                                                         \
        _Pragma("unroll")                                                     \
        for (int np = 0; np < 4; ++np)                                        \
            ldsm4(Bf[bf_][np], (bbuf_) + bRowOff[np]                          \
                  + ((uint32_t)((ks_) * 32 + bkb_l) ^ bXor[np]));             \
    }

    // ---- prologue: g0={A0,B0}, g1={B1}, g2={B2} ----
    ISSUE_A(0); ISSUE_B(0); cp_commit();
    ISSUE_B(1); cp_commit();
    ISSUE_B(2); cp_commit();

    uint32_t Af[2][4][4], Bf[2][4][4];

    for (int kc = 0; kc < NCH; ++kc) {
        CP_WAIT(2);
        __syncthreads();

        const int s    = kc / 3;
        const int dxp1 = kc % 3;
        const uint32_t abuf = sb + (uint32_t)(s & 1) * ABUF_BYTES;
        const uint32_t bbuf = sb + SMEM_B0 + (uint32_t)(kc & 3) * BBUF_BYTES;

        // prefetch ks=0 fragments, then issue next loads (overlaps LDSM latency)
        LOAD_A_FRAGS(0, abuf, dxp1, 0);
        LOAD_B_FRAGS(0, bbuf, 0);

        if (kc % 3 == 0 && (s + 1) < 6) ISSUE_A(s + 1);
        if (kc + 3 < NCH) ISSUE_B(kc + 3);
        cp_commit();

        #pragma unroll
        for (int ks = 0; ks < 4; ++ks) {
            const int cur = ks & 1;
            if (ks < 3) {
                LOAD_A_FRAGS(cur ^ 1, abuf, dxp1, ks + 1);
                LOAD_B_FRAGS(cur ^ 1, bbuf, ks + 1);
            }
            #pragma unroll
            for (int mt = 0; mt < 4; ++mt)
                #pragma unroll
                for (int np = 0; np < 4; ++np) {
                    mma_f16(acc[mt][np * 2],     Af[cur][mt], &Bf[cur][np][0]);
                    mma_f16(acc[mt][np * 2 + 1], Af[cur][mt], &Bf[cur][np][2]);
                }
        }
    }

    // ---- epilogue: direct STG ----
    float* Yb = Y + (((size_t)b * HW + h) * HW) * FOUT;
    #pragma unroll
    for (int mt = 0; mt < 4; ++mt)
        #pragma unroll
        for (int rg = 0; rg < 2; ++rg) {
            const int m = mw + mt * 16 + rg * 8 + (lane >> 2);
            float* yr = Yb + (size_t)m * FOUT + nw + (lane & 3) * 2;
            #pragma unroll
            for (int nt = 0; nt < 8; ++nt) {
                float2 v;
                v.x = acc[mt][nt][rg * 2];
                v.y = acc[mt][nt][rg * 2 + 1];
                *(float2*)(yr + nt * 8) = v;
            }
        }
    #undef ISSUE_A
    #undef ISSUE_B
    #undef LOAD_A_FRAGS
    #undef LOAD_B_FRAGS
}

// ---------------------------------------------------------------------------
extern "C" void kernel_launch(void* const* d_in, const int* in_sizes, int n_in,
                              void* d_out, int out_size) {
    const float* x     = (const float*)d_in[0];   // (8,128,128,128)
    const float* style = (const float*)d_in[1];   // (8,128)
    const float* kern  = (const float*)d_in[2];   // (3,3,128,128)
    float* y = (float*)d_out;

    cudaFuncSetAttribute(mdconv_hmma_kernel,
                         cudaFuncAttributeMaxDynamicSharedMemorySize, SMEM_TOTAL);

    split_x_kernel<<<(BATCH * HW * HW * CIN) / 8 / 256, 256>>>(x);
    wprep_kernel<<<dim3(FOUT, BATCH), 128>>>(style, kern);
    mdconv_hmma_kernel<<<dim3(HW, BATCH), 128, SMEM_TOTAL>>>(y);
}

// round 12
// speedup vs baseline: 1.0795x; 1.0487x over previous
#include <cuda_runtime.h>
#include <cuda_fp16.h>
#include <cstdint>

// StyleGAN2 modulated+demodulated conv on GB300 (sm_103 base target -> HMMA).
// x: (8,128,128,128) NHWC fp32, style: (8,128), kernel: (3,3,128,128) -> NHWC fp32
//
// Single-product fp16 GEMM: Y = fp16(X) * fp16(W_mod_demod), fp32 accum.
// K0 split_x: X fp32 -> fp16
// K1 wprep  : demod scale + modulate -> fp16 W, layout [b][f][k]
// K2 gemm   : per (h,b) CTA: M=128 (w), N=128 (f), K=1152.
//   A from 130-row shifted windows (6 stages; 3 dx taps via smem row offset).
//   B: 18 chunks of 64, 4-buffer cp.async ring, wait_group(2) (chunk kc only).
//   Issue strictly AFTER the barrier (R10's issue-before-sync raced).
//   4 warps, warp tile 64x64, 2 CTAs/SM.

#define HW    128
#define CIN   128
#define FOUT  128
#define BATCH 8
#define KK    1152
#define NCH   18

__device__ __half g_xh[BATCH * HW * HW * CIN];
__device__ __half g_wh[BATCH * FOUT * KK];

// ---------------- asm helpers ----------------
__device__ __forceinline__ uint32_t smem_u32(const void* p) {
    uint32_t a;
    asm("{ .reg .u64 t; cvta.to.shared.u64 t, %1; cvt.u32.u64 %0, t; }"
        : "=r"(a) : "l"(p));
    return a;
}
__device__ __forceinline__ void ldsm4(uint32_t* r, uint32_t addr) {
    asm volatile("ldmatrix.sync.aligned.m8n8.x4.shared.b16 {%0,%1,%2,%3}, [%4];"
                 : "=r"(r[0]), "=r"(r[1]), "=r"(r[2]), "=r"(r[3]) : "r"(addr));
}
__device__ __forceinline__ void mma_f16(float* c, const uint32_t* a, const uint32_t* b) {
    asm volatile(
        "mma.sync.aligned.m16n8k16.row.col.f32.f16.f16.f32 "
        "{%0,%1,%2,%3}, {%4,%5,%6,%7}, {%8,%9}, {%0,%1,%2,%3};"
        : "+f"(c[0]), "+f"(c[1]), "+f"(c[2]), "+f"(c[3])
        : "r"(a[0]), "r"(a[1]), "r"(a[2]), "r"(a[3]), "r"(b[0]), "r"(b[1]));
}
__device__ __forceinline__ void cp_async16z(uint32_t saddr, const void* gaddr,
                                            uint32_t src_size) {
    asm volatile("cp.async.cg.shared.global [%0], [%1], 16, %2;"
                 :: "r"(saddr), "l"(gaddr), "r"(src_size));
}
__device__ __forceinline__ void cp_async16(uint32_t saddr, const void* gaddr) {
    asm volatile("cp.async.cg.shared.global [%0], [%1], 16;"
                 :: "r"(saddr), "l"(gaddr));
}
__device__ __forceinline__ void cp_commit() { asm volatile("cp.async.commit_group;"); }
#define CP_WAIT(n) asm volatile("cp.async.wait_group %0;" :: "n"(n) : "memory")

// ---------------------------------------------------------------------------
// K0: X fp32 -> fp16 (8 floats/thread).
// ---------------------------------------------------------------------------
__global__ void split_x_kernel(const float* __restrict__ X) {
    size_t i = ((size_t)blockIdx.x * 256 + threadIdx.x) * 8;
    float4 v0 = *(const float4*)(X + i);
    float4 v1 = *(const float4*)(X + i + 4);
    __half2 h01 = __floats2half2_rn(v0.x, v0.y);
    __half2 h23 = __floats2half2_rn(v0.z, v0.w);
    __half2 h45 = __floats2half2_rn(v1.x, v1.y);
    __half2 h67 = __floats2half2_rn(v1.z, v1.w);
    uint4 o = make_uint4(*(uint32_t*)&h01, *(uint32_t*)&h23,
                         *(uint32_t*)&h45, *(uint32_t*)&h67);
    *(uint4*)(g_xh + i) = o;
}

// ---------------------------------------------------------------------------
// K1: fused demod scale + modulate -> fp16, layout [b][f][k].
// ---------------------------------------------------------------------------
__global__ void wprep_kernel(const float* __restrict__ style,
                             const float* __restrict__ kern) {
    const int f = blockIdx.x, b = blockIdx.y, c = threadIdx.x;
    const float st = style[b * CIN + c] + 1.0f;
    float wv[9];
    float ss = 0.0f;
    #pragma unroll
    for (int p = 0; p < 9; ++p) {
        float w = kern[(p * 128 + c) * 128 + f] * st;
        wv[p] = w;
        ss = fmaf(w, w, ss);
    }
    __shared__ float red[128];
    red[c] = ss;
    __syncthreads();
    #pragma unroll
    for (int s = 64; s > 0; s >>= 1) {
        if (c < s) red[c] += red[c + s];
        __syncthreads();
    }
    const float scale = rsqrtf(red[0] + 1e-8f);
    const size_t base = (size_t)(b * 128 + f) * KK;
    #pragma unroll
    for (int p = 0; p < 9; ++p)
        g_wh[base + p * 128 + c] = __float2half_rn(wv[p] * scale);
}

// ---------------------------------------------------------------------------
// K2: HMMA implicit GEMM with shifted-window A.
// grid (128 h, 8 b) x 128 threads (4 warps), 2 CTAs/SM.
// Warps 2(m) x 2(n), warp tile 64x64.
// SMEM: A windows 2 x 17408 (130 rows x 128B, SW128), B 4 x 16384.
// ---------------------------------------------------------------------------
#define ABUF_BYTES 17408
#define BBUF_BYTES 16384
#define SMEM_B0    (2 * ABUF_BYTES)               // 34816
#define SMEM_TOTAL (SMEM_B0 + 4 * BBUF_BYTES)     // 100352

__global__ __launch_bounds__(128, 2)
void mdconv_hmma_kernel(float* __restrict__ Y) {
    extern __shared__ __align__(1024) char smem[];
    const uint32_t sb  = smem_u32(smem);
    const int tid  = threadIdx.x;
    const int wid  = tid >> 5;
    const int lane = tid & 31;
    const int h = blockIdx.x;
    const int b = blockIdx.y;

    const int mw = (wid >> 1) * 64;     // warp m offset
    const int nw = (wid & 1) * 64;      // warp n offset

    const __half* xh_b = g_xh + (size_t)b * HW * HW * CIN;
    const __half* wh_b = g_wh + (size_t)b * FOUT * KK;

    // ---- ldmatrix per-lane invariants ----
    const int arow_l = (lane & 7) + ((lane >> 3) & 1) * 8;
    const int akb_l  = ((lane >> 4) & 1) * 16;
    const int brow_l = (lane & 7) + ((lane >> 4) & 1) * 8;
    const int bkb_l  = ((lane >> 3) & 1) * 16;

    int aRowBase[4];
    #pragma unroll
    for (int mt = 0; mt < 4; ++mt) aRowBase[mt] = mw + mt * 16 + arow_l;
    uint32_t bRowOff[4], bXor[4];
    #pragma unroll
    for (int np = 0; np < 4; ++np) {
        const int row = nw + np * 16 + brow_l;
        bRowOff[np] = (uint32_t)row * 128;
        bXor[np]    = (uint32_t)((row & 7) * 16);
    }

    float acc[4][8][4];
    #pragma unroll
    for (int i = 0; i < 4; ++i)
        #pragma unroll
        for (int j = 0; j < 8; ++j)
            #pragma unroll
            for (int q = 0; q < 4; ++q) acc[i][j][q] = 0.0f;

    // A window for stage s_: 130 rows (w=-1..128) x 64 ch of X[h+dy][.][c0..]
    #define ISSUE_A(s_)                                                       \
    {                                                                         \
        const uint32_t abuf = sb + (uint32_t)((s_) & 1) * ABUF_BYTES;         \
        const int dy_ = (s_) / 2 - 1;                                         \
        const int c0_ = ((s_) & 1) * 64;                                      \
        const int hh_ = h + dy_;                                              \
        const bool hok_ = (unsigned)hh_ < HW;                                 \
        _Pragma("unroll")                                                     \
        for (int t = 0; t < 8; ++t) {                                         \
            const int u = tid + 128 * t;                                      \
            const int row = u >> 3, seg = u & 7;                              \
            const int wq = row - 1;                                           \
            const bool ok = hok_ && ((unsigned)wq < HW);                      \
            const __half* ga = ok                                             \
                ? xh_b + (((size_t)hh_ * HW + wq) << 7) + c0_ + seg * 8       \
                : xh_b;                                                       \
            cp_async16z(abuf + row * 128 + ((seg * 16) ^ ((row & 7) * 16)),   \
                        ga, ok ? 16u : 0u);                                   \
        }                                                                     \
        if (tid < 16) {                                                       \
            const int u = 1024 + tid;                                         \
            const int row = u >> 3, seg = u & 7;                              \
            const int wq = row - 1;                                           \
            const bool ok = hok_ && ((unsigned)wq < HW);                      \
            const __half* ga = ok                                             \
                ? xh_b + (((size_t)hh_ * HW + wq) << 7) + c0_ + seg * 8       \
                : xh_b;                                                       \
            cp_async16z(abuf + row * 128 + ((seg * 16) ^ ((row & 7) * 16)),   \
                        ga, ok ? 16u : 0u);                                   \
        }                                                                     \
    }

    #define ISSUE_B(kc_)                                                      \
    {                                                                         \
        const uint32_t bbuf = sb + SMEM_B0                                    \
                            + (uint32_t)((kc_) & 3) * BBUF_BYTES;             \
        const int s_  = (kc_) / 3;                                            \
        const int p_  = (s_ / 2) * 3 + (kc_) % 3;                             \
        const int c0_ = (s_ & 1) * 64;                                        \
        _Pragma("unroll")                                                     \
        for (int t = 0; t < 8; ++t) {                                         \
            const int u = tid + 128 * t;                                      \
            const int f_ = u >> 3, seg = u & 7;                               \
            cp_async16(bbuf + f_ * 128 + ((seg * 16) ^ ((f_ & 7) * 16)),      \
                       wh_b + (size_t)f_ * KK + p_ * 128 + c0_ + seg * 8);    \
        }                                                                     \
    }

    // ---- prologue: g0={A0,B0}, g1={B1}, g2={B2} ----
    ISSUE_A(0); ISSUE_B(0); cp_commit();
    ISSUE_B(1); cp_commit();
    ISSUE_B(2); cp_commit();

    for (int kc = 0; kc < NCH; ++kc) {
        // wait(2): committed groups here = 3+kc; <=2 outstanding ->
        // groups 0..kc complete -> chunk kc's B and its A window resident.
        CP_WAIT(2);
        __syncthreads();

        const int s    = kc / 3;
        const int dxp1 = kc % 3;

        // Issue AFTER the barrier (overwritten buffers were last read at
        // iteration kc-1; the barrier above fences those reads).
        if (kc % 3 == 0 && (s + 1) < 6) ISSUE_A(s + 1);
        if (kc + 3 < NCH) ISSUE_B(kc + 3);
        cp_commit();

        const uint32_t abuf = sb + (uint32_t)(s & 1) * ABUF_BYTES;
        const uint32_t bbuf = sb + SMEM_B0 + (uint32_t)(kc & 3) * BBUF_BYTES;

        #pragma unroll
        for (int ks = 0; ks < 4; ++ks) {
            uint32_t Af[4][4], Bf[4][4];
            #pragma unroll
            for (int mt = 0; mt < 4; ++mt) {
                const int row = aRowBase[mt] + dxp1;
                const uint32_t off = (uint32_t)row * 128
                    + ((uint32_t)(ks * 32 + akb_l) ^ ((row & 7) * 16));
                ldsm4(Af[mt], abuf + off);
            }
            #pragma unroll
            for (int np = 0; np < 4; ++np)
                ldsm4(Bf[np], bbuf + bRowOff[np]
                      + ((uint32_t)(ks * 32 + bkb_l) ^ bXor[np]));
            #pragma unroll
            for (int mt = 0; mt < 4; ++mt)
                #pragma unroll
                for (int np = 0; np < 4; ++np) {
                    mma_f16(acc[mt][np * 2],     Af[mt], &Bf[np][0]);
                    mma_f16(acc[mt][np * 2 + 1], Af[mt], &Bf[np][2]);
                }
        }
    }

    // ---- epilogue: direct STG ----
    float* Yb = Y + (((size_t)b * HW + h) * HW) * FOUT;
    #pragma unroll
    for (int mt = 0; mt < 4; ++mt)
        #pragma unroll
        for (int rg = 0; rg < 2; ++rg) {
            const int m = mw + mt * 16 + rg * 8 + (lane >> 2);
            float* yr = Yb + (size_t)m * FOUT + nw + (lane & 3) * 2;
            #pragma unroll
            for (int nt = 0; nt < 8; ++nt) {
                float2 v;
                v.x = acc[mt][nt][rg * 2];
                v.y = acc[mt][nt][rg * 2 + 1];
                *(float2*)(yr + nt * 8) = v;
            }
        }
    #undef ISSUE_A
    #undef ISSUE_B
}

// ---------------------------------------------------------------------------
extern "C" void kernel_launch(void* const* d_in, const int* in_sizes, int n_in,
                              void* d_out, int out_size) {
    const float* x     = (const float*)d_in[0];   // (8,128,128,128)
    const float* style = (const float*)d_in[1];   // (8,128)
    const float* kern  = (const float*)d_in[2];   // (3,3,128,128)
    float* y = (float*)d_out;

    cudaFuncSetAttribute(mdconv_hmma_kernel,
                         cudaFuncAttributeMaxDynamicSharedMemorySize, SMEM_TOTAL);

    split_x_kernel<<<(BATCH * HW * HW * CIN) / 8 / 256, 256>>>(x);
    wprep_kernel<<<dim3(FOUT, BATCH), 128>>>(style, kern);
    mdconv_hmma_kernel<<<dim3(HW, BATCH), 128, SMEM_TOTAL>>>(y);
}